// round 10
// baseline (speedup 1.0000x reference)
#include <cuda_runtime.h>
#include <cuda_bf16.h>
#include <math.h>
#include <float.h>

// ---------------- Problem constants ----------------
#define N_ANCH   25200
#define ROW_LEN  117          // 4 box + 1 obj + 80 cls + 32 coef
#define NC       80
#define NM       32
#define TOPK     1024
#define MAX_DET  300
#define IMG      640
#define PROTO_HW 160
#define PROTO_PX (PROTO_HW*PROTO_HW)   // 25600
#define CONF_T   0.25f
#define IOU_T    0.45f
#define MAX_WH   7680.0f

#define CAND_CAP 4096

// Output layout (all float32, concatenated):
// masks_f [300*640*640], masks_bool [300*640*640], fb [300*4], fs [300], fcls [300]
#define PLANE      ((long long)MAX_DET * IMG * IMG)        // 122,880,000
#define OF_BOOL    (PLANE)
#define OF_FB      (2*PLANE)
#define OF_FS      (2*PLANE + MAX_DET*4)
#define OF_FCLS    (2*PLANE + MAX_DET*4 + MAX_DET)

// ---------------- Device scratch ----------------
__device__ unsigned            g_hist[65536];
__device__ unsigned            g_ss[N_ANCH];           // sortable score bits
__device__ float               g_topscore[TOPK];
__device__ float               g_box[TOPK*4];          // xyxy
__device__ float4              g_nbox[TOPK];           // xyxy + cls*MAX_WH
__device__ int                 g_cls[TOPK];
__device__ int                 g_oidx[TOPK];
__device__ unsigned            g_supT[32*TOPK];        // [col_chunk][row] transposed bitmask
__device__ float               g_fcoef[MAX_DET*NM];
__device__ float               g_fb[MAX_DET*4];
__device__ int                 g_fvalid[MAX_DET];
__device__ float               g_m[MAX_DET*PROTO_PX];  // sigmoid mask logits @160x160

// ---------------- helpers ----------------
__device__ __forceinline__ unsigned f2s(float f) {
    unsigned u = __float_as_uint(f);
    return (u & 0x80000000u) ? ~u : (u | 0x80000000u);
}
__device__ __forceinline__ float s2f(unsigned s) {
    unsigned u = (s & 0x80000000u) ? (s & 0x7FFFFFFFu) : ~s;
    return __uint_as_float(u);
}

// ---------------- K1: per-anchor scores + histogram (warp per anchor) ----------------
__global__ void k_score(const float* __restrict__ pred) {
    int gid = blockIdx.x*blockDim.x + threadIdx.x;
    int gw = gid >> 5;
    int lane = gid & 31;
    if (gw >= N_ANCH) return;
    const float* r = pred + (long long)gw*ROW_LEN;
    float obj = __ldg(r + 4);
    float v = -1e30f;
    float c0 = __ldg(r + 5 + lane) * obj;
    if (c0 > v) v = c0;
    float c1 = __ldg(r + 37 + lane) * obj;
    if (c1 > v) v = c1;
    if (lane < 16) {
        float c2 = __ldg(r + 69 + lane) * obj;
        if (c2 > v) v = c2;
    }
    #pragma unroll
    for (int off = 16; off; off >>= 1)
        v = fmaxf(v, __shfl_xor_sync(0xffffffffu, v, off));
    if (lane == 0) {
        bool valid = (obj > CONF_T) && (v > CONF_T);
        float score = valid ? v : -1.0f;
        unsigned s = f2s(score);
        g_ss[gw] = s;
        if (valid) atomicAdd(&g_hist[s >> 16], 1u);
    }
}

// ---------------- K2: fused threshold + gather + sort + extract (single block) ----------------
__global__ void __launch_bounds__(1024) k_select(const float* __restrict__ pred) {
    __shared__ unsigned long long cand[CAND_CAP];   // 32 KB
    __shared__ unsigned wsum[32];
    __shared__ unsigned fine64[64];
    __shared__ unsigned s_thresh;
    __shared__ unsigned s_cumbase, s_target;
    __shared__ int s_coarse;
    __shared__ int s_cnt;
    int tid = threadIdx.x;
    int lane = tid & 31, wid = tid >> 5;

    if (tid == 0) { s_cnt = 0; s_coarse = -1; s_thresh = 0x10000u; }

    // --- coarse per-thread partial sums over 64 buckets (descending order) ---
    unsigned s;
    {
        int hi = 65535 - tid*64;
        s = 0;
        #pragma unroll 8
        for (int k = 0; k < 64; k++) s += g_hist[hi - k];
    }
    // --- block inclusive scan of s ---
    unsigned x = s;
    #pragma unroll
    for (int o = 1; o < 32; o <<= 1) {
        unsigned y = __shfl_up_sync(0xffffffffu, x, o);
        if (lane >= o) x += y;
    }
    if (lane == 31) wsum[wid] = x;
    __syncthreads();
    if (wid == 0) {
        unsigned w = wsum[lane];
        #pragma unroll
        for (int o = 1; o < 32; o <<= 1) {
            unsigned y = __shfl_up_sync(0xffffffffu, w, o);
            if (lane >= o) w += y;
        }
        wsum[lane] = w;
    }
    __syncthreads();
    unsigned cum = x + ((wid == 0) ? 0u : wsum[wid-1]);   // inclusive prefix
    unsigned total = wsum[31];
    unsigned target = total < TOPK ? total : TOPK;
    if (target > 0 && (cum - s) < target && target <= cum) {
        s_coarse = tid; s_cumbase = cum - s; s_target = target;
    }
    __syncthreads();
    int coarse = s_coarse;
    if (coarse >= 0 && tid < 64)
        fine64[tid] = g_hist[65535 - coarse*64 - tid];
    __syncthreads();
    if (tid == 0 && coarse >= 0) {
        unsigned c2 = s_cumbase, tg = s_target;
        int k = 0;
        while (k < 63) { c2 += fine64[k]; if (c2 >= tg) break; k++; }
        if (c2 < tg) c2 += fine64[k];   // defensive: never read past 63
        s_thresh = (unsigned)(65535 - coarse*64 - k);
    }
    __syncthreads();
    unsigned thr = s_thresh;

    // --- gather into smem ---
    for (int i = tid; i < N_ANCH; i += 1024) {
        unsigned ss = g_ss[i];
        if ((ss >> 16) >= thr) {
            int pos = atomicAdd(&s_cnt, 1);
            if (pos < CAND_CAP)
                cand[pos] = ((unsigned long long)ss << 32) | (unsigned)(N_ANCH - 1 - i);
        }
    }
    __syncthreads();
    int cnt = s_cnt; if (cnt > CAND_CAP) cnt = CAND_CAP;
    int S = 1024;
    while (S < cnt) S <<= 1;     // 1024/2048/4096
    for (int i = tid; i < S; i += 1024)
        if (i >= cnt) cand[i] = 0ULL;
    __syncthreads();

    // --- bitonic sort descending over S entries ---
    for (unsigned k = 2; k <= (unsigned)S; k <<= 1) {
        for (unsigned j = k >> 1; j > 0; j >>= 1) {
            for (unsigned i = tid; i < (unsigned)S; i += 1024) {
                unsigned ixj = i ^ j;
                if (ixj > i) {
                    unsigned long long a = cand[i], b = cand[ixj];
                    bool descRun = (i & k) == 0;
                    bool doSwap = descRun ? (a < b) : (a > b);
                    if (doSwap) { cand[i] = b; cand[ixj] = a; }
                }
            }
            __syncthreads();
        }
    }

    // --- extract top-1024 (warp-cooperative argmax + box decode) ---
    for (int e = wid; e < TOPK; e += 32) {
        unsigned long long key = cand[e];
        float score; int idx;
        if (key == 0ULL) { score = -1.0f; idx = 0; }
        else {
            score = s2f((unsigned)(key >> 32));
            idx = N_ANCH - 1 - (int)(unsigned)(key & 0xFFFFFFFFu);
        }
        const float* r = pred + (long long)idx*ROW_LEN;
        float obj = __ldg(r + 4);
        float v = -1e30f; int j = 127;
        float c0 = __ldg(r + 5 + lane) * obj;
        if (c0 > v) { v = c0; j = lane; }
        float c1 = __ldg(r + 37 + lane) * obj;
        if (c1 > v) { v = c1; j = lane + 32; }
        if (lane < 16) {
            float c2 = __ldg(r + 69 + lane) * obj;
            if (c2 > v) { v = c2; j = lane + 64; }
        }
        #pragma unroll
        for (int off = 16; off; off >>= 1) {
            float ov = __shfl_xor_sync(0xffffffffu, v, off);
            int   oj = __shfl_xor_sync(0xffffffffu, j, off);
            if (ov > v || (ov == v && oj < j)) { v = ov; j = oj; }
        }
        if (lane == 0) {
            g_topscore[e] = score;
            g_oidx[e] = idx;
            g_cls[e] = j;
            float cx = r[0], cy = r[1], w = r[2], h = r[3];
            float x1 = cx - w*0.5f, y1 = cy - h*0.5f, x2 = cx + w*0.5f, y2 = cy + h*0.5f;
            g_box[e*4+0] = x1; g_box[e*4+1] = y1; g_box[e*4+2] = x2; g_box[e*4+3] = y2;
            float off_ = (float)j * MAX_WH;
            g_nbox[e] = make_float4(x1+off_, y1+off_, x2+off_, y2+off_);
        }
    }
}

// ---------------- K3: suppression matrix (warp per row, smem boxes, ballot, transposed store) ----------------
__global__ void __launch_bounds__(256) k_sup() {
    __shared__ float4 sb[TOPK];      // 16 KB
    int tid = threadIdx.x, lane = tid & 31, w8 = tid >> 5;
    for (int i = tid; i < TOPK; i += 256) sb[i] = g_nbox[i];
    __syncthreads();
    int row = blockIdx.x*8 + w8;     // 0..1023
    float4 a = sb[row];
    float a1 = (a.z - a.x)*(a.w - a.y);
    unsigned myword = 0;
    #pragma unroll 4
    for (int w = 0; w < 32; w++) {
        int j = (w << 5) + lane;
        float4 b = sb[j];
        float ix = fmaxf(fminf(a.z, b.z) - fmaxf(a.x, b.x), 0.f);
        float iy = fmaxf(fminf(a.w, b.w) - fmaxf(a.y, b.y), 0.f);
        float inter = ix*iy;
        float a2 = (b.z - b.x)*(b.w - b.y);
        float iou = inter / (a1 + a2 - inter + 1e-7f);
        unsigned bal = __ballot_sync(0xffffffffu, iou > IOU_T);
        if (lane == w) myword = bal;
    }
    // transposed: g_supT[col_chunk][row]; lane holds word for col_chunk == lane.
    // bit j of g_supT[c*1024+row] == (IoU(row, c*32+j) > thr). IoU symmetric.
    g_supT[lane*TOPK + row] = myword;
}

// ---------------- K4: NMS resolve (transposed coalesced loads + bounded ballot resolve) + finalize ----------------
__global__ void k_nms_final(const float* __restrict__ pred, float* __restrict__ out) {
    __shared__ int s_det[MAX_DET];
    __shared__ int s_ndet;
    int tid = threadIdx.x;
    if (tid < 32) {
        int lane = tid;
        unsigned lowmask = (1u << lane) - 1u;          // lane 0 -> 0
        unsigned pre = 0;    // bit r = candidate (r*32+lane) suppressed by earlier kept
        int n = 0;
        unsigned fut[32];
        float scn;
        // prefetch chunk 0 (fully coalesced: lane-contiguous)
        #pragma unroll
        for (int r = 0; r < 32; r++) fut[r] = g_supT[r*32 + lane];
        scn = g_topscore[lane];
        for (int c = 0; c < 32 && n < MAX_DET; c++) {
            unsigned cur[32];
            #pragma unroll
            for (int r = 0; r < 32; r++) cur[r] = fut[r];
            float sc = scn;
            if (c < 31) {   // prefetch next chunk behind the resolve
                #pragma unroll
                for (int r = 0; r < 32; r++)
                    fut[r] = g_supT[(c+1)*TOPK + r*32 + lane];
                scn = g_topscore[(c+1)*32 + lane];
            }
            bool alive = (sc > CONF_T) && !((pre >> c) & 1u);
            unsigned wb = cur[c];      // bits j: IoU(my candidate, c*32+j) > thr
            unsigned rem = __ballot_sync(0xffffffffu, alive);
            unsigned keep = 0;
            // bounded greedy resolve: <=32 iterations, rem uniform across warp
            #pragma unroll 1
            for (int it = 0; it < 32; it++) {
                if (rem == 0u) break;
                int b = __ffs(rem) - 1;
                keep |= (1u << b);
                unsigned supb = __ballot_sync(0xffffffffu, (wb >> b) & 1u);
                rem &= ~supb;
                rem &= ~(1u << b);
            }
            unsigned mybit = (keep >> lane) & 1u;
            int pos = n + __popc(keep & lowmask);
            if (mybit && pos < MAX_DET) s_det[pos] = c*32 + lane;
            n += __popc(keep);
            // propagate suppression to future chunks (pure ALU)
            #pragma unroll
            for (int r = 0; r < 32; r++)
                if (r > c && (keep & cur[r])) pre |= (1u << r);
        }
        if (lane == 0) s_ndet = n < MAX_DET ? n : MAX_DET;
    }
    __syncthreads();
    int n = s_ndet;
    for (int d = tid; d < MAX_DET; d += blockDim.x) {
        if (d < n) {
            int ci = s_det[d];
            int oi = g_oidx[ci];
            float fs = g_topscore[ci];
            float b0 = g_box[ci*4+0], b1 = g_box[ci*4+1], b2 = g_box[ci*4+2], b3 = g_box[ci*4+3];
            int cls = g_cls[ci];
            g_fvalid[d] = 1;
            g_fb[d*4+0]=b0; g_fb[d*4+1]=b1; g_fb[d*4+2]=b2; g_fb[d*4+3]=b3;
            out[OF_FB + d*4+0]=b0; out[OF_FB + d*4+1]=b1; out[OF_FB + d*4+2]=b2; out[OF_FB + d*4+3]=b3;
            out[OF_FS + d] = fs;
            out[OF_FCLS + d] = (float)cls;
            const float* r = pred + (long long)oi*ROW_LEN + 5 + NC;
            for (int k = 0; k < NM; k++) g_fcoef[d*NM+k] = r[k];
        } else {
            g_fvalid[d] = 0;
            g_fb[d*4+0]=0.f; g_fb[d*4+1]=0.f; g_fb[d*4+2]=0.f; g_fb[d*4+3]=0.f;
            out[OF_FB + d*4+0]=0.f; out[OF_FB + d*4+1]=0.f; out[OF_FB + d*4+2]=0.f; out[OF_FB + d*4+3]=0.f;
            out[OF_FS + d] = 0.f;
            out[OF_FCLS + d] = -1.0f;
            for (int k = 0; k < NM; k++) g_fcoef[d*NM+k] = 0.f;
        }
    }
}

// ---------------- K5: mask GEMM + sigmoid (300x32 @ 32x25600) ----------------
#define GD 16   // dets per block
__global__ void k_gemm(const float* __restrict__ protos) {
    __shared__ float sp[NM][256];
    __shared__ float fc[GD][NM];
    int tid = threadIdx.x;
    int p0 = blockIdx.x * 256;
    int d0 = blockIdx.y * GD;
    for (int idx = tid; idx < GD*NM; idx += 256) {
        int dd = idx / NM, k = idx % NM;
        int d = d0 + dd;
        fc[dd][k] = (d < MAX_DET) ? g_fcoef[d*NM + k] : 0.f;
    }
    #pragma unroll 8
    for (int k = 0; k < NM; k++) sp[k][tid] = protos[(long long)k*PROTO_PX + p0 + tid];
    __syncthreads();
    int p = p0 + tid;
    #pragma unroll 4
    for (int dd = 0; dd < GD; dd++) {
        int d = d0 + dd;
        if (d >= MAX_DET) break;
        float acc = 0.f;
        #pragma unroll
        for (int k = 0; k < NM; k++) acc = fmaf(fc[dd][k], sp[k][tid], acc);
        g_m[(long long)d*PROTO_PX + p] = 1.0f / (1.0f + expf(-acc));
    }
}

// ---------------- K6: interior-only resize + crop + write ----------------
__global__ void k_interior(float* __restrict__ out) {
    int d = blockIdx.x;
    if (!g_fvalid[d]) return;
    float x1 = g_fb[d*4+0], y1 = g_fb[d*4+1], x2 = g_fb[d*4+2], y2 = g_fb[d*4+3];
    int r0 = max(0, (int)ceilf(y1));
    int re = min(IMG, (int)ceilf(y2));
    int c0 = max(0, (int)ceilf(x1));
    int ce = min(IMG, (int)ceilf(x2));
    if (r0 >= re || c0 >= ce) return;
    int nc = ce - c0;
    int total = (re - r0) * nc;
    const float* mrow = g_m + (long long)d * PROTO_PX;
    for (int idx = threadIdx.x; idx < total; idx += blockDim.x) {
        int rr = idx / nc;
        int cc = idx - rr*nc;
        int row = r0 + rr, col = c0 + cc;
        float ys = fminf(fmaxf(((float)row + 0.5f)*0.25f - 0.5f, 0.f), (float)(PROTO_HW-1));
        int yA = (int)ys; float fy = ys - (float)yA;
        int yB = yA + 1; if (yB > PROTO_HW-1) yB = PROTO_HW-1;
        float xs = fminf(fmaxf(((float)col + 0.5f)*0.25f - 0.5f, 0.f), (float)(PROTO_HW-1));
        int xA = (int)xs; float fx = xs - (float)xA;
        int xB = xA + 1; if (xB > PROTO_HW-1) xB = PROTO_HW-1;
        float a = mrow[yA*PROTO_HW + xA]*(1.0f - fy) + mrow[yB*PROTO_HW + xA]*fy;
        float b = mrow[yA*PROTO_HW + xB]*(1.0f - fy) + mrow[yB*PROTO_HW + xB]*fy;
        float o = a*(1.0f - fx) + b*fx;
        long long base = (long long)d*(IMG*IMG) + (long long)row*IMG + col;
        out[base] = o;
        out[OF_BOOL + base] = (o > 0.5f) ? 1.0f : 0.0f;
    }
}

// ---------------- launch ----------------
extern "C" void kernel_launch(void* const* d_in, const int* in_sizes, int n_in,
                              void* d_out, int out_size) {
    const float* pred   = (const float*)d_in[0];
    const float* protos = (const float*)d_in[1];
    float* out = (float*)d_out;

    static cudaStream_t s2 = nullptr;
    static cudaEvent_t evF = nullptr, evJ = nullptr;
    if (!s2) {
        cudaStreamCreateWithFlags(&s2, cudaStreamNonBlocking);
        cudaEventCreateWithFlags(&evF, cudaEventDisableTiming);
        cudaEventCreateWithFlags(&evJ, cudaEventDisableTiming);
    }

    void* histp = nullptr;
    cudaGetSymbolAddress(&histp, g_hist);

    // Fork: zero-fill both mask planes (983 MB) concurrently with the det chain.
    cudaEventRecord(evF, 0);
    cudaStreamWaitEvent(s2, evF, 0);
    cudaMemsetAsync(out, 0, (size_t)2 * PLANE * sizeof(float), s2);
    cudaEventRecord(evJ, s2);

    // Detection chain on the default stream.
    cudaMemsetAsync(histp, 0, 65536 * sizeof(unsigned), 0);
    k_score<<<(N_ANCH*32 + 255)/256, 256>>>(pred);
    k_select<<<1, 1024>>>(pred);
    k_sup<<<TOPK/8, 256>>>();
    k_nms_final<<<1, 256>>>(pred, out);
    k_gemm<<<dim3(PROTO_PX/256, (MAX_DET + GD - 1)/GD), 256>>>(protos);

    // Join: interior writes overwrite zeros only after the zero-fill completes.
    cudaStreamWaitEvent(0, evJ, 0);
    k_interior<<<MAX_DET, 256>>>(out);
}

// round 11
// speedup vs baseline: 1.0450x; 1.0450x over previous
#include <cuda_runtime.h>
#include <cuda_bf16.h>
#include <math.h>
#include <float.h>

// ---------------- Problem constants ----------------
#define N_ANCH   25200
#define ROW_LEN  117          // 4 box + 1 obj + 80 cls + 32 coef
#define NC       80
#define NM       32
#define TOPK     1024
#define MAX_DET  300
#define IMG      640
#define PROTO_HW 160
#define PROTO_PX (PROTO_HW*PROTO_HW)   // 25600
#define CONF_T   0.25f
#define IOU_T    0.45f
#define MAX_WH   7680.0f

#define CAND_CAP 4096

// Output layout (all float32, concatenated):
// masks_f [300*640*640], masks_bool [300*640*640], fb [300*4], fs [300], fcls [300]
#define PLANE      ((long long)MAX_DET * IMG * IMG)        // 122,880,000
#define OF_BOOL    (PLANE)
#define OF_FB      (2*PLANE)
#define OF_FS      (2*PLANE + MAX_DET*4)
#define OF_FCLS    (2*PLANE + MAX_DET*4 + MAX_DET)

// ---------------- Device scratch ----------------
__device__ unsigned            g_hist[65536];
__device__ unsigned            g_ss[N_ANCH];           // sortable score bits
__device__ float               g_topscore[TOPK];
__device__ float               g_box[TOPK*4];          // xyxy
__device__ float4              g_nbox[TOPK];           // xyxy + cls*MAX_WH
__device__ int                 g_cls[TOPK];
__device__ int                 g_oidx[TOPK];
__device__ unsigned            g_supT[32*TOPK];        // [col_chunk][row] transposed bitmask
__device__ float               g_fcoef[MAX_DET*NM];
__device__ float               g_fb[MAX_DET*4];
__device__ int                 g_fvalid[MAX_DET];
__device__ float               g_m[MAX_DET*PROTO_PX];  // sigmoid mask logits @160x160

// ---------------- helpers ----------------
__device__ __forceinline__ unsigned f2s(float f) {
    unsigned u = __float_as_uint(f);
    return (u & 0x80000000u) ? ~u : (u | 0x80000000u);
}
__device__ __forceinline__ float s2f(unsigned s) {
    unsigned u = (s & 0x80000000u) ? (s & 0x7FFFFFFFu) : ~s;
    return __uint_as_float(u);
}

// ---------------- K1: per-anchor scores + histogram (warp per anchor) ----------------
__global__ void k_score(const float* __restrict__ pred) {
    int gid = blockIdx.x*blockDim.x + threadIdx.x;
    int gw = gid >> 5;
    int lane = gid & 31;
    if (gw >= N_ANCH) return;
    const float* r = pred + (long long)gw*ROW_LEN;
    float obj = __ldg(r + 4);
    float v = -1e30f;
    float c0 = __ldg(r + 5 + lane) * obj;
    if (c0 > v) v = c0;
    float c1 = __ldg(r + 37 + lane) * obj;
    if (c1 > v) v = c1;
    if (lane < 16) {
        float c2 = __ldg(r + 69 + lane) * obj;
        if (c2 > v) v = c2;
    }
    #pragma unroll
    for (int off = 16; off; off >>= 1)
        v = fmaxf(v, __shfl_xor_sync(0xffffffffu, v, off));
    if (lane == 0) {
        bool valid = (obj > CONF_T) && (v > CONF_T);
        float score = valid ? v : -1.0f;
        unsigned s = f2s(score);
        g_ss[gw] = s;
        if (valid) atomicAdd(&g_hist[s >> 16], 1u);
    }
}

// ---------------- K2: fused threshold + gather + sort + extract (single block) ----------------
__global__ void __launch_bounds__(1024) k_select(const float* __restrict__ pred) {
    __shared__ unsigned long long cand[CAND_CAP];   // 32 KB
    __shared__ unsigned wsum[32];
    __shared__ unsigned fine64[64];
    __shared__ unsigned s_thresh;
    __shared__ unsigned s_cumbase, s_target;
    __shared__ int s_coarse;
    __shared__ int s_cnt;
    int tid = threadIdx.x;
    int lane = tid & 31, wid = tid >> 5;

    if (tid == 0) { s_cnt = 0; s_coarse = -1; s_thresh = 0x10000u; }

    // --- coarse per-thread partial sums over 64 buckets (descending order) ---
    unsigned s;
    {
        int hi = 65535 - tid*64;
        s = 0;
        #pragma unroll 8
        for (int k = 0; k < 64; k++) s += g_hist[hi - k];
    }
    // --- block inclusive scan of s ---
    unsigned x = s;
    #pragma unroll
    for (int o = 1; o < 32; o <<= 1) {
        unsigned y = __shfl_up_sync(0xffffffffu, x, o);
        if (lane >= o) x += y;
    }
    if (lane == 31) wsum[wid] = x;
    __syncthreads();
    if (wid == 0) {
        unsigned w = wsum[lane];
        #pragma unroll
        for (int o = 1; o < 32; o <<= 1) {
            unsigned y = __shfl_up_sync(0xffffffffu, w, o);
            if (lane >= o) w += y;
        }
        wsum[lane] = w;
    }
    __syncthreads();
    unsigned cum = x + ((wid == 0) ? 0u : wsum[wid-1]);   // inclusive prefix
    unsigned total = wsum[31];
    unsigned target = total < TOPK ? total : TOPK;
    if (target > 0 && (cum - s) < target && target <= cum) {
        s_coarse = tid; s_cumbase = cum - s; s_target = target;
    }
    __syncthreads();
    int coarse = s_coarse;
    if (coarse >= 0 && tid < 64)
        fine64[tid] = g_hist[65535 - coarse*64 - tid];
    __syncthreads();
    if (tid == 0 && coarse >= 0) {
        unsigned c2 = s_cumbase, tg = s_target;
        int k = 0;
        while (k < 63) { c2 += fine64[k]; if (c2 >= tg) break; k++; }
        if (c2 < tg) c2 += fine64[k];   // defensive: never read past 63
        s_thresh = (unsigned)(65535 - coarse*64 - k);
    }
    __syncthreads();
    unsigned thr = s_thresh;

    // --- gather into smem ---
    for (int i = tid; i < N_ANCH; i += 1024) {
        unsigned ss = g_ss[i];
        if ((ss >> 16) >= thr) {
            int pos = atomicAdd(&s_cnt, 1);
            if (pos < CAND_CAP)
                cand[pos] = ((unsigned long long)ss << 32) | (unsigned)(N_ANCH - 1 - i);
        }
    }
    __syncthreads();
    int cnt = s_cnt; if (cnt > CAND_CAP) cnt = CAND_CAP;
    int S = 1024;
    while (S < cnt) S <<= 1;     // 1024/2048/4096
    for (int i = tid; i < S; i += 1024)
        if (i >= cnt) cand[i] = 0ULL;
    __syncthreads();

    // --- bitonic sort descending over S entries ---
    for (unsigned k = 2; k <= (unsigned)S; k <<= 1) {
        for (unsigned j = k >> 1; j > 0; j >>= 1) {
            for (unsigned i = tid; i < (unsigned)S; i += 1024) {
                unsigned ixj = i ^ j;
                if (ixj > i) {
                    unsigned long long a = cand[i], b = cand[ixj];
                    bool descRun = (i & k) == 0;
                    bool doSwap = descRun ? (a < b) : (a > b);
                    if (doSwap) { cand[i] = b; cand[ixj] = a; }
                }
            }
            __syncthreads();
        }
    }

    // --- extract top-1024 (warp-cooperative argmax + box decode) ---
    for (int e = wid; e < TOPK; e += 32) {
        unsigned long long key = cand[e];
        float score; int idx;
        if (key == 0ULL) { score = -1.0f; idx = 0; }
        else {
            score = s2f((unsigned)(key >> 32));
            idx = N_ANCH - 1 - (int)(unsigned)(key & 0xFFFFFFFFu);
        }
        const float* r = pred + (long long)idx*ROW_LEN;
        float obj = __ldg(r + 4);
        float v = -1e30f; int j = 127;
        float c0 = __ldg(r + 5 + lane) * obj;
        if (c0 > v) { v = c0; j = lane; }
        float c1 = __ldg(r + 37 + lane) * obj;
        if (c1 > v) { v = c1; j = lane + 32; }
        if (lane < 16) {
            float c2 = __ldg(r + 69 + lane) * obj;
            if (c2 > v) { v = c2; j = lane + 64; }
        }
        #pragma unroll
        for (int off = 16; off; off >>= 1) {
            float ov = __shfl_xor_sync(0xffffffffu, v, off);
            int   oj = __shfl_xor_sync(0xffffffffu, j, off);
            if (ov > v || (ov == v && oj < j)) { v = ov; j = oj; }
        }
        if (lane == 0) {
            g_topscore[e] = score;
            g_oidx[e] = idx;
            g_cls[e] = j;
            float cx = r[0], cy = r[1], w = r[2], h = r[3];
            float x1 = cx - w*0.5f, y1 = cy - h*0.5f, x2 = cx + w*0.5f, y2 = cy + h*0.5f;
            g_box[e*4+0] = x1; g_box[e*4+1] = y1; g_box[e*4+2] = x2; g_box[e*4+3] = y2;
            float off_ = (float)j * MAX_WH;
            g_nbox[e] = make_float4(x1+off_, y1+off_, x2+off_, y2+off_);
        }
    }
}

// ---------------- K3: suppression matrix (warp per row, smem boxes, ballot, transposed store) ----------------
__global__ void __launch_bounds__(256) k_sup() {
    __shared__ float4 sb[TOPK];      // 16 KB
    int tid = threadIdx.x, lane = tid & 31, w8 = tid >> 5;
    for (int i = tid; i < TOPK; i += 256) sb[i] = g_nbox[i];
    __syncthreads();
    int row = blockIdx.x*8 + w8;     // 0..1023
    float4 a = sb[row];
    float a1 = (a.z - a.x)*(a.w - a.y);
    unsigned myword = 0;
    #pragma unroll 4
    for (int w = 0; w < 32; w++) {
        int j = (w << 5) + lane;
        float4 b = sb[j];
        float ix = fmaxf(fminf(a.z, b.z) - fmaxf(a.x, b.x), 0.f);
        float iy = fmaxf(fminf(a.w, b.w) - fmaxf(a.y, b.y), 0.f);
        float inter = ix*iy;
        float a2 = (b.z - b.x)*(b.w - b.y);
        float iou = inter / (a1 + a2 - inter + 1e-7f);
        unsigned bal = __ballot_sync(0xffffffffu, iou > IOU_T);
        if (lane == w) myword = bal;
    }
    // transposed: g_supT[col_chunk][row]; lane holds word for col_chunk == lane.
    // bit j of g_supT[c*1024+row] == (IoU(row, c*32+j) > thr). IoU symmetric.
    g_supT[lane*TOPK + row] = myword;
}

// ---------------- K4: NMS resolve (fixpoint-ballot, early exit) + finalize ----------------
__global__ void k_nms_final(const float* __restrict__ pred, float* __restrict__ out) {
    __shared__ int s_det[MAX_DET];
    __shared__ int s_ndet;
    int tid = threadIdx.x;
    if (tid < 32) {
        int lane = tid;
        unsigned lowmask = (1u << lane) - 1u;          // lane 0 -> 0
        unsigned pre = 0;    // bit r = candidate (r*32+lane) suppressed by earlier kept
        int n = 0;
        for (int c = 0; c < 32 && n < MAX_DET; c++) {
            // lane-contiguous coalesced loads of chunk c (MLP=32)
            unsigned cur[32];
            #pragma unroll
            for (int r = 0; r < 32; r++)
                cur[r] = g_supT[c*TOPK + r*32 + lane];
            float sc = g_topscore[c*32 + lane];
            bool alive = (sc > CONF_T) && !((pre >> c) & 1u);
            unsigned wb = cur[c];      // bits j: IoU(my candidate, c*32+j) > thr
            // Jacobi fixpoint of: keep(b) = alive(b) && no kept j<b suppresses b.
            // Unique fixpoint == greedy NMS; converges in <= chain-depth (<=32) iters.
            unsigned keep = __ballot_sync(0xffffffffu, alive);
            #pragma unroll 1
            for (int it = 0; it < 32; it++) {
                bool kb = alive && ((keep & wb & lowmask) == 0u);
                unsigned nk = __ballot_sync(0xffffffffu, kb);
                if (nk == keep) break;
                keep = nk;
            }
            unsigned mybit = (keep >> lane) & 1u;
            int pos = n + __popc(keep & lowmask);
            if (mybit && pos < MAX_DET) s_det[pos] = c*32 + lane;
            n += __popc(keep);
            // propagate suppression to future chunks (pure ALU)
            #pragma unroll
            for (int r = 0; r < 32; r++)
                if (r > c && (keep & cur[r])) pre |= (1u << r);
        }
        if (lane == 0) s_ndet = n < MAX_DET ? n : MAX_DET;
    }
    __syncthreads();
    int n = s_ndet;
    for (int d = tid; d < MAX_DET; d += blockDim.x) {
        if (d < n) {
            int ci = s_det[d];
            int oi = g_oidx[ci];
            float fs = g_topscore[ci];
            float b0 = g_box[ci*4+0], b1 = g_box[ci*4+1], b2 = g_box[ci*4+2], b3 = g_box[ci*4+3];
            int cls = g_cls[ci];
            g_fvalid[d] = 1;
            g_fb[d*4+0]=b0; g_fb[d*4+1]=b1; g_fb[d*4+2]=b2; g_fb[d*4+3]=b3;
            out[OF_FB + d*4+0]=b0; out[OF_FB + d*4+1]=b1; out[OF_FB + d*4+2]=b2; out[OF_FB + d*4+3]=b3;
            out[OF_FS + d] = fs;
            out[OF_FCLS + d] = (float)cls;
            const float* r = pred + (long long)oi*ROW_LEN + 5 + NC;
            for (int k = 0; k < NM; k++) g_fcoef[d*NM+k] = r[k];
        } else {
            g_fvalid[d] = 0;
            g_fb[d*4+0]=0.f; g_fb[d*4+1]=0.f; g_fb[d*4+2]=0.f; g_fb[d*4+3]=0.f;
            out[OF_FB + d*4+0]=0.f; out[OF_FB + d*4+1]=0.f; out[OF_FB + d*4+2]=0.f; out[OF_FB + d*4+3]=0.f;
            out[OF_FS + d] = 0.f;
            out[OF_FCLS + d] = -1.0f;
            for (int k = 0; k < NM; k++) g_fcoef[d*NM+k] = 0.f;
        }
    }
}

// ---------------- K5: mask GEMM + sigmoid (300x32 @ 32x25600) ----------------
#define GD 16   // dets per block
__global__ void k_gemm(const float* __restrict__ protos) {
    __shared__ float sp[NM][256];
    __shared__ float fc[GD][NM];
    int tid = threadIdx.x;
    int p0 = blockIdx.x * 256;
    int d0 = blockIdx.y * GD;
    for (int idx = tid; idx < GD*NM; idx += 256) {
        int dd = idx / NM, k = idx % NM;
        int d = d0 + dd;
        fc[dd][k] = (d < MAX_DET) ? g_fcoef[d*NM + k] : 0.f;
    }
    #pragma unroll 8
    for (int k = 0; k < NM; k++) sp[k][tid] = protos[(long long)k*PROTO_PX + p0 + tid];
    __syncthreads();
    int p = p0 + tid;
    #pragma unroll 4
    for (int dd = 0; dd < GD; dd++) {
        int d = d0 + dd;
        if (d >= MAX_DET) break;
        float acc = 0.f;
        #pragma unroll
        for (int k = 0; k < NM; k++) acc = fmaf(fc[dd][k], sp[k][tid], acc);
        g_m[(long long)d*PROTO_PX + p] = 1.0f / (1.0f + expf(-acc));
    }
}

// ---------------- K6: interior-only resize + crop + write ----------------
__global__ void k_interior(float* __restrict__ out) {
    int d = blockIdx.x;
    if (!g_fvalid[d]) return;
    float x1 = g_fb[d*4+0], y1 = g_fb[d*4+1], x2 = g_fb[d*4+2], y2 = g_fb[d*4+3];
    int r0 = max(0, (int)ceilf(y1));
    int re = min(IMG, (int)ceilf(y2));
    int c0 = max(0, (int)ceilf(x1));
    int ce = min(IMG, (int)ceilf(x2));
    if (r0 >= re || c0 >= ce) return;
    int nc = ce - c0;
    int total = (re - r0) * nc;
    const float* mrow = g_m + (long long)d * PROTO_PX;
    for (int idx = threadIdx.x; idx < total; idx += blockDim.x) {
        int rr = idx / nc;
        int cc = idx - rr*nc;
        int row = r0 + rr, col = c0 + cc;
        float ys = fminf(fmaxf(((float)row + 0.5f)*0.25f - 0.5f, 0.f), (float)(PROTO_HW-1));
        int yA = (int)ys; float fy = ys - (float)yA;
        int yB = yA + 1; if (yB > PROTO_HW-1) yB = PROTO_HW-1;
        float xs = fminf(fmaxf(((float)col + 0.5f)*0.25f - 0.5f, 0.f), (float)(PROTO_HW-1));
        int xA = (int)xs; float fx = xs - (float)xA;
        int xB = xA + 1; if (xB > PROTO_HW-1) xB = PROTO_HW-1;
        float a = mrow[yA*PROTO_HW + xA]*(1.0f - fy) + mrow[yB*PROTO_HW + xA]*fy;
        float b = mrow[yA*PROTO_HW + xB]*(1.0f - fy) + mrow[yB*PROTO_HW + xB]*fy;
        float o = a*(1.0f - fx) + b*fx;
        long long base = (long long)d*(IMG*IMG) + (long long)row*IMG + col;
        out[base] = o;
        out[OF_BOOL + base] = (o > 0.5f) ? 1.0f : 0.0f;
    }
}

// ---------------- launch ----------------
extern "C" void kernel_launch(void* const* d_in, const int* in_sizes, int n_in,
                              void* d_out, int out_size) {
    const float* pred   = (const float*)d_in[0];
    const float* protos = (const float*)d_in[1];
    float* out = (float*)d_out;

    static cudaStream_t s2 = nullptr;
    static cudaEvent_t evF = nullptr, evJ = nullptr;
    if (!s2) {
        cudaStreamCreateWithFlags(&s2, cudaStreamNonBlocking);
        cudaEventCreateWithFlags(&evF, cudaEventDisableTiming);
        cudaEventCreateWithFlags(&evJ, cudaEventDisableTiming);
    }

    void* histp = nullptr;
    cudaGetSymbolAddress(&histp, g_hist);

    // Fork: zero-fill both mask planes (983 MB) concurrently with the det chain.
    cudaEventRecord(evF, 0);
    cudaStreamWaitEvent(s2, evF, 0);
    cudaMemsetAsync(out, 0, (size_t)2 * PLANE * sizeof(float), s2);
    cudaEventRecord(evJ, s2);

    // Detection chain on the default stream.
    cudaMemsetAsync(histp, 0, 65536 * sizeof(unsigned), 0);
    k_score<<<(N_ANCH*32 + 255)/256, 256>>>(pred);
    k_select<<<1, 1024>>>(pred);
    k_sup<<<TOPK/8, 256>>>();
    k_nms_final<<<1, 256>>>(pred, out);
    k_gemm<<<dim3(PROTO_PX/256, (MAX_DET + GD - 1)/GD), 256>>>(protos);

    // Join: interior writes overwrite zeros only after the zero-fill completes.
    cudaStreamWaitEvent(0, evJ, 0);
    k_interior<<<MAX_DET, 256>>>(out);
}

// round 12
// speedup vs baseline: 1.1437x; 1.0944x over previous
#include <cuda_runtime.h>
#include <cuda_bf16.h>
#include <math.h>
#include <float.h>

// ---------------- Problem constants ----------------
#define N_ANCH   25200
#define ROW_LEN  117          // 4 box + 1 obj + 80 cls + 32 coef
#define NC       80
#define NM       32
#define TOPK     1024
#define MAX_DET  300
#define IMG      640
#define PROTO_HW 160
#define PROTO_PX (PROTO_HW*PROTO_HW)   // 25600
#define CONF_T   0.25f
#define IOU_T    0.45f
#define MAX_WH   7680.0f

#define CAND_CAP 4096

// Output layout (all float32, concatenated):
// masks_f [300*640*640], masks_bool [300*640*640], fb [300*4], fs [300], fcls [300]
#define PLANE      ((long long)MAX_DET * IMG * IMG)        // 122,880,000
#define OF_BOOL    (PLANE)
#define OF_FB      (2*PLANE)
#define OF_FS      (2*PLANE + MAX_DET*4)
#define OF_FCLS    (2*PLANE + MAX_DET*4 + MAX_DET)

// ---------------- Device scratch ----------------
__device__ unsigned            g_hist[65536];
__device__ unsigned            g_ss[N_ANCH];           // sortable score bits
__device__ float               g_topscore[TOPK];
__device__ float               g_box[TOPK*4];          // xyxy
__device__ float4              g_nbox[TOPK];           // xyxy + cls*MAX_WH
__device__ int                 g_cls[TOPK];
__device__ int                 g_oidx[TOPK];
__device__ unsigned            g_supT[32*TOPK];        // [col_chunk][row] transposed bitmask
__device__ float               g_fcoef[MAX_DET*NM];
__device__ float               g_fb[MAX_DET*4];
__device__ int                 g_fvalid[MAX_DET];
__device__ float               g_m[MAX_DET*PROTO_PX];  // sigmoid mask logits @160x160

// ---------------- helpers ----------------
__device__ __forceinline__ unsigned f2s(float f) {
    unsigned u = __float_as_uint(f);
    return (u & 0x80000000u) ? ~u : (u | 0x80000000u);
}
__device__ __forceinline__ float s2f(unsigned s) {
    unsigned u = (s & 0x80000000u) ? (s & 0x7FFFFFFFu) : ~s;
    return __uint_as_float(u);
}

// ---------------- K1: per-anchor scores + histogram (warp per anchor) ----------------
__global__ void k_score(const float* __restrict__ pred) {
    int gid = blockIdx.x*blockDim.x + threadIdx.x;
    int gw = gid >> 5;
    int lane = gid & 31;
    if (gw >= N_ANCH) return;
    const float* r = pred + (long long)gw*ROW_LEN;
    float obj = __ldg(r + 4);
    float v = -1e30f;
    float c0 = __ldg(r + 5 + lane) * obj;
    if (c0 > v) v = c0;
    float c1 = __ldg(r + 37 + lane) * obj;
    if (c1 > v) v = c1;
    if (lane < 16) {
        float c2 = __ldg(r + 69 + lane) * obj;
        if (c2 > v) v = c2;
    }
    #pragma unroll
    for (int off = 16; off; off >>= 1)
        v = fmaxf(v, __shfl_xor_sync(0xffffffffu, v, off));
    if (lane == 0) {
        bool valid = (obj > CONF_T) && (v > CONF_T);
        float score = valid ? v : -1.0f;
        unsigned s = f2s(score);
        g_ss[gw] = s;
        if (valid) atomicAdd(&g_hist[s >> 16], 1u);
    }
}

// ---------------- K2: fused threshold + gather + sort + extract (single block) ----------------
__global__ void __launch_bounds__(1024) k_select(const float* __restrict__ pred) {
    __shared__ unsigned long long cand[CAND_CAP];   // 32 KB
    __shared__ unsigned wsum[32];
    __shared__ unsigned fine64[64];
    __shared__ unsigned s_thresh;
    __shared__ unsigned s_cumbase, s_target;
    __shared__ int s_coarse;
    __shared__ int s_cnt;
    int tid = threadIdx.x;
    int lane = tid & 31, wid = tid >> 5;

    if (tid == 0) { s_cnt = 0; s_coarse = -1; s_thresh = 0x10000u; }

    // --- coarse per-thread partial sums over 64 buckets (descending order) ---
    unsigned s;
    {
        int hi = 65535 - tid*64;
        s = 0;
        #pragma unroll 8
        for (int k = 0; k < 64; k++) s += g_hist[hi - k];
    }
    // --- block inclusive scan of s ---
    unsigned x = s;
    #pragma unroll
    for (int o = 1; o < 32; o <<= 1) {
        unsigned y = __shfl_up_sync(0xffffffffu, x, o);
        if (lane >= o) x += y;
    }
    if (lane == 31) wsum[wid] = x;
    __syncthreads();
    if (wid == 0) {
        unsigned w = wsum[lane];
        #pragma unroll
        for (int o = 1; o < 32; o <<= 1) {
            unsigned y = __shfl_up_sync(0xffffffffu, w, o);
            if (lane >= o) w += y;
        }
        wsum[lane] = w;
    }
    __syncthreads();
    unsigned cum = x + ((wid == 0) ? 0u : wsum[wid-1]);   // inclusive prefix
    unsigned total = wsum[31];
    unsigned target = total < TOPK ? total : TOPK;
    if (target > 0 && (cum - s) < target && target <= cum) {
        s_coarse = tid; s_cumbase = cum - s; s_target = target;
    }
    __syncthreads();
    int coarse = s_coarse;
    if (coarse >= 0 && tid < 64)
        fine64[tid] = g_hist[65535 - coarse*64 - tid];
    __syncthreads();
    if (tid == 0 && coarse >= 0) {
        unsigned c2 = s_cumbase, tg = s_target;
        int k = 0;
        while (k < 63) { c2 += fine64[k]; if (c2 >= tg) break; k++; }
        if (c2 < tg) c2 += fine64[k];   // defensive: never read past 63
        s_thresh = (unsigned)(65535 - coarse*64 - k);
    }
    __syncthreads();
    unsigned thr = s_thresh;

    // --- gather into smem ---
    for (int i = tid; i < N_ANCH; i += 1024) {
        unsigned ss = g_ss[i];
        if ((ss >> 16) >= thr) {
            int pos = atomicAdd(&s_cnt, 1);
            if (pos < CAND_CAP)
                cand[pos] = ((unsigned long long)ss << 32) | (unsigned)(N_ANCH - 1 - i);
        }
    }
    __syncthreads();
    int cnt = s_cnt; if (cnt > CAND_CAP) cnt = CAND_CAP;
    int S = 1024;
    while (S < cnt) S <<= 1;     // 1024/2048/4096
    for (int i = tid; i < S; i += 1024)
        if (i >= cnt) cand[i] = 0ULL;
    __syncthreads();

    // --- bitonic sort descending over S entries ---
    for (unsigned k = 2; k <= (unsigned)S; k <<= 1) {
        for (unsigned j = k >> 1; j > 0; j >>= 1) {
            for (unsigned i = tid; i < (unsigned)S; i += 1024) {
                unsigned ixj = i ^ j;
                if (ixj > i) {
                    unsigned long long a = cand[i], b = cand[ixj];
                    bool descRun = (i & k) == 0;
                    bool doSwap = descRun ? (a < b) : (a > b);
                    if (doSwap) { cand[i] = b; cand[ixj] = a; }
                }
            }
            __syncthreads();
        }
    }

    // --- extract top-1024 (warp-cooperative argmax + box decode) ---
    for (int e = wid; e < TOPK; e += 32) {
        unsigned long long key = cand[e];
        float score; int idx;
        if (key == 0ULL) { score = -1.0f; idx = 0; }
        else {
            score = s2f((unsigned)(key >> 32));
            idx = N_ANCH - 1 - (int)(unsigned)(key & 0xFFFFFFFFu);
        }
        const float* r = pred + (long long)idx*ROW_LEN;
        float obj = __ldg(r + 4);
        float v = -1e30f; int j = 127;
        float c0 = __ldg(r + 5 + lane) * obj;
        if (c0 > v) { v = c0; j = lane; }
        float c1 = __ldg(r + 37 + lane) * obj;
        if (c1 > v) { v = c1; j = lane + 32; }
        if (lane < 16) {
            float c2 = __ldg(r + 69 + lane) * obj;
            if (c2 > v) { v = c2; j = lane + 64; }
        }
        #pragma unroll
        for (int off = 16; off; off >>= 1) {
            float ov = __shfl_xor_sync(0xffffffffu, v, off);
            int   oj = __shfl_xor_sync(0xffffffffu, j, off);
            if (ov > v || (ov == v && oj < j)) { v = ov; j = oj; }
        }
        if (lane == 0) {
            g_topscore[e] = score;
            g_oidx[e] = idx;
            g_cls[e] = j;
            float cx = r[0], cy = r[1], w = r[2], h = r[3];
            float x1 = cx - w*0.5f, y1 = cy - h*0.5f, x2 = cx + w*0.5f, y2 = cy + h*0.5f;
            g_box[e*4+0] = x1; g_box[e*4+1] = y1; g_box[e*4+2] = x2; g_box[e*4+3] = y2;
            float off_ = (float)j * MAX_WH;
            g_nbox[e] = make_float4(x1+off_, y1+off_, x2+off_, y2+off_);
        }
    }
}

// ---------------- K3: suppression matrix (warp per row, smem boxes, ballot, transposed store) ----------------
__global__ void __launch_bounds__(256) k_sup() {
    __shared__ float4 sb[TOPK];      // 16 KB
    int tid = threadIdx.x, lane = tid & 31, w8 = tid >> 5;
    for (int i = tid; i < TOPK; i += 256) sb[i] = g_nbox[i];
    __syncthreads();
    int row = blockIdx.x*8 + w8;     // 0..1023
    float4 a = sb[row];
    float a1 = (a.z - a.x)*(a.w - a.y);
    unsigned myword = 0;
    #pragma unroll 4
    for (int w = 0; w < 32; w++) {
        int j = (w << 5) + lane;
        float4 b = sb[j];
        float ix = fmaxf(fminf(a.z, b.z) - fmaxf(a.x, b.x), 0.f);
        float iy = fmaxf(fminf(a.w, b.w) - fmaxf(a.y, b.y), 0.f);
        float inter = ix*iy;
        float a2 = (b.z - b.x)*(b.w - b.y);
        float iou = inter / (a1 + a2 - inter + 1e-7f);
        unsigned bal = __ballot_sync(0xffffffffu, iou > IOU_T);
        if (lane == w) myword = bal;
    }
    // transposed: g_supT[col_chunk][row]; lane holds word for col_chunk == lane.
    // bit j of g_supT[c*1024+row] == (IoU(row, c*32+j) > thr). IoU symmetric.
    g_supT[lane*TOPK + row] = myword;
}

// ---------------- K4: NMS resolve (fixpoint-ballot, early exit) + finalize ----------------
__global__ void k_nms_final(const float* __restrict__ pred, float* __restrict__ out) {
    __shared__ int s_det[MAX_DET];
    __shared__ int s_ndet;
    int tid = threadIdx.x;
    if (tid < 32) {
        int lane = tid;
        unsigned lowmask = (1u << lane) - 1u;          // lane 0 -> 0
        unsigned pre = 0;    // bit r = candidate (r*32+lane) suppressed by earlier kept
        int n = 0;
        for (int c = 0; c < 32 && n < MAX_DET; c++) {
            // lane-contiguous coalesced loads of chunk c (MLP=32)
            unsigned cur[32];
            #pragma unroll
            for (int r = 0; r < 32; r++)
                cur[r] = g_supT[c*TOPK + r*32 + lane];
            float sc = g_topscore[c*32 + lane];
            bool alive = (sc > CONF_T) && !((pre >> c) & 1u);
            unsigned wb = cur[c];      // bits j: IoU(my candidate, c*32+j) > thr
            // Jacobi fixpoint of: keep(b) = alive(b) && no kept j<b suppresses b.
            // Unique fixpoint == greedy NMS; converges in <= chain-depth (<=32) iters.
            unsigned keep = __ballot_sync(0xffffffffu, alive);
            #pragma unroll 1
            for (int it = 0; it < 32; it++) {
                bool kb = alive && ((keep & wb & lowmask) == 0u);
                unsigned nk = __ballot_sync(0xffffffffu, kb);
                if (nk == keep) break;
                keep = nk;
            }
            unsigned mybit = (keep >> lane) & 1u;
            int pos = n + __popc(keep & lowmask);
            if (mybit && pos < MAX_DET) s_det[pos] = c*32 + lane;
            n += __popc(keep);
            // propagate suppression to future chunks (pure ALU)
            #pragma unroll
            for (int r = 0; r < 32; r++)
                if (r > c && (keep & cur[r])) pre |= (1u << r);
        }
        if (lane == 0) s_ndet = n < MAX_DET ? n : MAX_DET;
    }
    __syncthreads();
    int n = s_ndet;
    for (int d = tid; d < MAX_DET; d += blockDim.x) {
        if (d < n) {
            int ci = s_det[d];
            int oi = g_oidx[ci];
            float fs = g_topscore[ci];
            float b0 = g_box[ci*4+0], b1 = g_box[ci*4+1], b2 = g_box[ci*4+2], b3 = g_box[ci*4+3];
            int cls = g_cls[ci];
            g_fvalid[d] = 1;
            g_fb[d*4+0]=b0; g_fb[d*4+1]=b1; g_fb[d*4+2]=b2; g_fb[d*4+3]=b3;
            out[OF_FB + d*4+0]=b0; out[OF_FB + d*4+1]=b1; out[OF_FB + d*4+2]=b2; out[OF_FB + d*4+3]=b3;
            out[OF_FS + d] = fs;
            out[OF_FCLS + d] = (float)cls;
            const float* r = pred + (long long)oi*ROW_LEN + 5 + NC;
            for (int k = 0; k < NM; k++) g_fcoef[d*NM+k] = r[k];
        } else {
            g_fvalid[d] = 0;
            g_fb[d*4+0]=0.f; g_fb[d*4+1]=0.f; g_fb[d*4+2]=0.f; g_fb[d*4+3]=0.f;
            out[OF_FB + d*4+0]=0.f; out[OF_FB + d*4+1]=0.f; out[OF_FB + d*4+2]=0.f; out[OF_FB + d*4+3]=0.f;
            out[OF_FS + d] = 0.f;
            out[OF_FCLS + d] = -1.0f;
            for (int k = 0; k < NM; k++) g_fcoef[d*NM+k] = 0.f;
        }
    }
}

// ---------------- K5: mask GEMM + sigmoid (300x32 @ 32x25600) ----------------
#define GD 16   // dets per block
__global__ void k_gemm(const float* __restrict__ protos) {
    __shared__ float sp[NM][256];
    __shared__ float fc[GD][NM];
    int tid = threadIdx.x;
    int p0 = blockIdx.x * 256;
    int d0 = blockIdx.y * GD;
    for (int idx = tid; idx < GD*NM; idx += 256) {
        int dd = idx / NM, k = idx % NM;
        int d = d0 + dd;
        fc[dd][k] = (d < MAX_DET) ? g_fcoef[d*NM + k] : 0.f;
    }
    #pragma unroll 8
    for (int k = 0; k < NM; k++) sp[k][tid] = protos[(long long)k*PROTO_PX + p0 + tid];
    __syncthreads();
    int p = p0 + tid;
    #pragma unroll 4
    for (int dd = 0; dd < GD; dd++) {
        int d = d0 + dd;
        if (d >= MAX_DET) break;
        float acc = 0.f;
        #pragma unroll
        for (int k = 0; k < NM; k++) acc = fmaf(fc[dd][k], sp[k][tid], acc);
        g_m[(long long)d*PROTO_PX + p] = 1.0f / (1.0f + expf(-acc));
    }
}

// ---------------- K6: single-pass resize + crop + write (whole planes, no memset) ----------------
__global__ void k_resize(float* __restrict__ out) {
    int d = blockIdx.y;
    int row = blockIdx.x;
    int t = threadIdx.x;              // 160 threads
    __shared__ float rb[PROTO_HW];

    bool val = g_fvalid[d] != 0;
    float x1 = g_fb[d*4+0], y1 = g_fb[d*4+1], x2 = g_fb[d*4+2], y2 = g_fb[d*4+3];
    float rowf = (float)row;
    bool rowin = val && (rowf >= y1) && (rowf < y2);   // uniform across block

    long long base = (long long)d * (IMG*IMG) + (long long)row * IMG;
    int c0 = t*4;
    if (rowin) {
        float ys = (rowf + 0.5f)*0.25f - 0.5f;
        ys = fminf(fmaxf(ys, 0.f), (float)(PROTO_HW-1));
        int yA = (int)ys;
        float fy = ys - (float)yA;
        int yB = yA + 1; if (yB > PROTO_HW-1) yB = PROTO_HW-1;
        const float* mrow = &g_m[(long long)d*PROTO_PX];
        rb[t] = mrow[yA*PROTO_HW + t]*(1.0f - fy) + mrow[yB*PROTO_HW + t]*fy;
        __syncthreads();
        float4 vf, vb;
        float* pf = (float*)&vf;
        float* pb = (float*)&vb;
        #pragma unroll
        for (int k = 0; k < 4; k++) {
            int col = c0 + k;
            float colf = (float)col;
            float xs = (colf + 0.5f)*0.25f - 0.5f;
            xs = fminf(fmaxf(xs, 0.f), (float)(PROTO_HW-1));
            int xA = (int)xs;
            float fx = xs - (float)xA;
            int xB = xA + 1; if (xB > PROTO_HW-1) xB = PROTO_HW-1;
            float v = rb[xA]*(1.0f - fx) + rb[xB]*fx;
            bool inx = (colf >= x1) && (colf < x2);
            float o = inx ? v : 0.f;
            pf[k] = o;
            pb[k] = (o > 0.5f) ? 1.0f : 0.0f;
        }
        *(float4*)(out + base + c0) = vf;
        *(float4*)(out + OF_BOOL + base + c0) = vb;
    } else {
        float4 z = make_float4(0.f, 0.f, 0.f, 0.f);
        *(float4*)(out + base + c0) = z;
        *(float4*)(out + OF_BOOL + base + c0) = z;
    }
}

// ---------------- launch ----------------
extern "C" void kernel_launch(void* const* d_in, const int* in_sizes, int n_in,
                              void* d_out, int out_size) {
    const float* pred   = (const float*)d_in[0];
    const float* protos = (const float*)d_in[1];
    float* out = (float*)d_out;

    void* histp = nullptr;
    cudaGetSymbolAddress(&histp, g_hist);

    cudaMemsetAsync(histp, 0, 65536 * sizeof(unsigned), 0);
    k_score<<<(N_ANCH*32 + 255)/256, 256>>>(pred);
    k_select<<<1, 1024>>>(pred);
    k_sup<<<TOPK/8, 256>>>();
    k_nms_final<<<1, 256>>>(pred, out);
    k_gemm<<<dim3(PROTO_PX/256, (MAX_DET + GD - 1)/GD), 256>>>(protos);
    k_resize<<<dim3(IMG, MAX_DET), PROTO_HW>>>(out);
}

// round 13
// speedup vs baseline: 1.2321x; 1.0773x over previous
#include <cuda_runtime.h>
#include <cuda_bf16.h>
#include <math.h>
#include <float.h>

// ---------------- Problem constants ----------------
#define N_ANCH   25200
#define ROW_LEN  117          // 4 box + 1 obj + 80 cls + 32 coef
#define NC       80
#define NM       32
#define TOPK     1024
#define MAX_DET  300
#define IMG      640
#define PROTO_HW 160
#define PROTO_PX (PROTO_HW*PROTO_HW)   // 25600
#define CONF_T   0.25f
#define IOU_T    0.45f
#define MAX_WH   7680.0f

#define CAND_CAP 4096

// Output layout (all float32, concatenated):
// masks_f [300*640*640], masks_bool [300*640*640], fb [300*4], fs [300], fcls [300]
#define PLANE      ((long long)MAX_DET * IMG * IMG)        // 122,880,000
#define OF_BOOL    (PLANE)
#define OF_FB      (2*PLANE)
#define OF_FS      (2*PLANE + MAX_DET*4)
#define OF_FCLS    (2*PLANE + MAX_DET*4 + MAX_DET)

// ---------------- Device scratch ----------------
__device__ unsigned            g_hist[65536];
__device__ unsigned            g_ss[N_ANCH];           // sortable score bits
__device__ float               g_topscore[TOPK];
__device__ float               g_box[TOPK*4];          // xyxy
__device__ float4              g_nbox[TOPK];           // xyxy + cls*MAX_WH
__device__ int                 g_cls[TOPK];
__device__ int                 g_oidx[TOPK];
__device__ unsigned            g_supT[32*TOPK];        // [col_chunk][row] transposed bitmask
__device__ float               g_fcoef[MAX_DET*NM];
__device__ float               g_fb[MAX_DET*4];
__device__ int                 g_fvalid[MAX_DET];
__device__ float               g_m[MAX_DET*PROTO_PX];  // sigmoid mask logits @160x160

// ---------------- helpers ----------------
__device__ __forceinline__ unsigned f2s(float f) {
    unsigned u = __float_as_uint(f);
    return (u & 0x80000000u) ? ~u : (u | 0x80000000u);
}
__device__ __forceinline__ float s2f(unsigned s) {
    unsigned u = (s & 0x80000000u) ? (s & 0x7FFFFFFFu) : ~s;
    return __uint_as_float(u);
}

// ---------------- K1: per-anchor scores + histogram (warp per anchor) ----------------
__global__ void k_score(const float* __restrict__ pred) {
    int gid = blockIdx.x*blockDim.x + threadIdx.x;
    int gw = gid >> 5;
    int lane = gid & 31;
    if (gw >= N_ANCH) return;
    const float* r = pred + (long long)gw*ROW_LEN;
    float obj = __ldg(r + 4);
    float v = -1e30f;
    float c0 = __ldg(r + 5 + lane) * obj;
    if (c0 > v) v = c0;
    float c1 = __ldg(r + 37 + lane) * obj;
    if (c1 > v) v = c1;
    if (lane < 16) {
        float c2 = __ldg(r + 69 + lane) * obj;
        if (c2 > v) v = c2;
    }
    #pragma unroll
    for (int off = 16; off; off >>= 1)
        v = fmaxf(v, __shfl_xor_sync(0xffffffffu, v, off));
    if (lane == 0) {
        bool valid = (obj > CONF_T) && (v > CONF_T);
        float score = valid ? v : -1.0f;
        unsigned s = f2s(score);
        g_ss[gw] = s;
        if (valid) atomicAdd(&g_hist[s >> 16], 1u);
    }
}

// ---------------- K2: fused threshold + gather + sort + extract (single block) ----------------
__global__ void __launch_bounds__(1024) k_select(const float* __restrict__ pred) {
    __shared__ unsigned long long cand[CAND_CAP];   // 32 KB
    __shared__ unsigned wsum[32];
    __shared__ unsigned fine64[64];
    __shared__ unsigned s_thresh;
    __shared__ unsigned s_cumbase, s_target;
    __shared__ int s_coarse;
    __shared__ int s_cnt;
    int tid = threadIdx.x;
    int lane = tid & 31, wid = tid >> 5;

    if (tid == 0) { s_cnt = 0; s_coarse = -1; s_thresh = 0x10000u; }

    // --- coarse per-thread partial sums over 64 buckets (descending order) ---
    unsigned s;
    {
        int hi = 65535 - tid*64;
        s = 0;
        #pragma unroll 8
        for (int k = 0; k < 64; k++) s += g_hist[hi - k];
    }
    // --- block inclusive scan of s ---
    unsigned x = s;
    #pragma unroll
    for (int o = 1; o < 32; o <<= 1) {
        unsigned y = __shfl_up_sync(0xffffffffu, x, o);
        if (lane >= o) x += y;
    }
    if (lane == 31) wsum[wid] = x;
    __syncthreads();
    if (wid == 0) {
        unsigned w = wsum[lane];
        #pragma unroll
        for (int o = 1; o < 32; o <<= 1) {
            unsigned y = __shfl_up_sync(0xffffffffu, w, o);
            if (lane >= o) w += y;
        }
        wsum[lane] = w;
    }
    __syncthreads();
    unsigned cum = x + ((wid == 0) ? 0u : wsum[wid-1]);   // inclusive prefix
    unsigned total = wsum[31];
    unsigned target = total < TOPK ? total : TOPK;
    if (target > 0 && (cum - s) < target && target <= cum) {
        s_coarse = tid; s_cumbase = cum - s; s_target = target;
    }
    __syncthreads();
    int coarse = s_coarse;
    if (coarse >= 0 && tid < 64)
        fine64[tid] = g_hist[65535 - coarse*64 - tid];
    __syncthreads();
    if (tid == 0 && coarse >= 0) {
        unsigned c2 = s_cumbase, tg = s_target;
        int k = 0;
        while (k < 63) { c2 += fine64[k]; if (c2 >= tg) break; k++; }
        if (c2 < tg) c2 += fine64[k];   // defensive: never read past 63
        s_thresh = (unsigned)(65535 - coarse*64 - k);
    }
    __syncthreads();
    unsigned thr = s_thresh;

    // --- gather into smem ---
    for (int i = tid; i < N_ANCH; i += 1024) {
        unsigned ss = g_ss[i];
        if ((ss >> 16) >= thr) {
            int pos = atomicAdd(&s_cnt, 1);
            if (pos < CAND_CAP)
                cand[pos] = ((unsigned long long)ss << 32) | (unsigned)(N_ANCH - 1 - i);
        }
    }
    __syncthreads();
    int cnt = s_cnt; if (cnt > CAND_CAP) cnt = CAND_CAP;
    int S = 1024;
    while (S < cnt) S <<= 1;     // 1024/2048/4096
    for (int i = tid; i < S; i += 1024)
        if (i >= cnt) cand[i] = 0ULL;
    __syncthreads();

    // --- bitonic sort descending over S entries ---
    for (unsigned k = 2; k <= (unsigned)S; k <<= 1) {
        for (unsigned j = k >> 1; j > 0; j >>= 1) {
            for (unsigned i = tid; i < (unsigned)S; i += 1024) {
                unsigned ixj = i ^ j;
                if (ixj > i) {
                    unsigned long long a = cand[i], b = cand[ixj];
                    bool descRun = (i & k) == 0;
                    bool doSwap = descRun ? (a < b) : (a > b);
                    if (doSwap) { cand[i] = b; cand[ixj] = a; }
                }
            }
            __syncthreads();
        }
    }

    // --- extract top-1024: thread-per-row (independent unrolled loads, high MLP) ---
    {
        unsigned long long key = cand[tid];
        float score; int idx;
        if (key == 0ULL) { score = -1.0f; idx = 0; }
        else {
            score = s2f((unsigned)(key >> 32));
            idx = N_ANCH - 1 - (int)(unsigned)(key & 0xFFFFFFFFu);
        }
        const float* r = pred + (long long)idx*ROW_LEN;
        float obj = __ldg(r + 4);
        float v = -1e30f; int j = 0;
        #pragma unroll 8
        for (int c = 0; c < NC; c++) {
            float t = __ldg(r + 5 + c) * obj;
            if (t > v) { v = t; j = c; }
        }
        g_topscore[tid] = score;
        g_oidx[tid] = idx;
        g_cls[tid] = j;
        float cx = __ldg(r+0), cy = __ldg(r+1), w = __ldg(r+2), h = __ldg(r+3);
        float x1 = cx - w*0.5f, y1 = cy - h*0.5f, x2 = cx + w*0.5f, y2 = cy + h*0.5f;
        g_box[tid*4+0] = x1; g_box[tid*4+1] = y1; g_box[tid*4+2] = x2; g_box[tid*4+3] = y2;
        float off_ = (float)j * MAX_WH;
        g_nbox[tid] = make_float4(x1+off_, y1+off_, x2+off_, y2+off_);
    }
}

// ---------------- K3: suppression matrix (warp per row, smem boxes, ballot, transposed store) ----------------
__global__ void __launch_bounds__(256) k_sup() {
    __shared__ float4 sb[TOPK];      // 16 KB
    int tid = threadIdx.x, lane = tid & 31, w8 = tid >> 5;
    for (int i = tid; i < TOPK; i += 256) sb[i] = g_nbox[i];
    __syncthreads();
    int row = blockIdx.x*8 + w8;     // 0..1023
    float4 a = sb[row];
    float a1 = (a.z - a.x)*(a.w - a.y);
    unsigned myword = 0;
    #pragma unroll 4
    for (int w = 0; w < 32; w++) {
        int j = (w << 5) + lane;
        float4 b = sb[j];
        float ix = fmaxf(fminf(a.z, b.z) - fmaxf(a.x, b.x), 0.f);
        float iy = fmaxf(fminf(a.w, b.w) - fmaxf(a.y, b.y), 0.f);
        float inter = ix*iy;
        float a2 = (b.z - b.x)*(b.w - b.y);
        float iou = inter / (a1 + a2 - inter + 1e-7f);
        unsigned bal = __ballot_sync(0xffffffffu, iou > IOU_T);
        if (lane == w) myword = bal;
    }
    // transposed: g_supT[col_chunk][row]; lane holds word for col_chunk == lane.
    g_supT[lane*TOPK + row] = myword;
}

// ---------------- K4: NMS resolve (fixpoint-ballot, early exit) + finalize ----------------
__global__ void k_nms_final(const float* __restrict__ pred, float* __restrict__ out) {
    __shared__ int s_det[MAX_DET];
    __shared__ int s_ndet;
    int tid = threadIdx.x;
    if (tid < 32) {
        int lane = tid;
        unsigned lowmask = (1u << lane) - 1u;          // lane 0 -> 0
        unsigned pre = 0;    // bit r = candidate (r*32+lane) suppressed by earlier kept
        int n = 0;
        for (int c = 0; c < 32 && n < MAX_DET; c++) {
            // lane-contiguous coalesced loads of chunk c (MLP=32)
            unsigned cur[32];
            #pragma unroll
            for (int r = 0; r < 32; r++)
                cur[r] = g_supT[c*TOPK + r*32 + lane];
            float sc = g_topscore[c*32 + lane];
            bool alive = (sc > CONF_T) && !((pre >> c) & 1u);
            unsigned wb = cur[c];      // bits j: IoU(my candidate, c*32+j) > thr
            // Jacobi fixpoint of: keep(b) = alive(b) && no kept j<b suppresses b.
            unsigned keep = __ballot_sync(0xffffffffu, alive);
            #pragma unroll 1
            for (int it = 0; it < 32; it++) {
                bool kb = alive && ((keep & wb & lowmask) == 0u);
                unsigned nk = __ballot_sync(0xffffffffu, kb);
                if (nk == keep) break;
                keep = nk;
            }
            unsigned mybit = (keep >> lane) & 1u;
            int pos = n + __popc(keep & lowmask);
            if (mybit && pos < MAX_DET) s_det[pos] = c*32 + lane;
            n += __popc(keep);
            // propagate suppression to future chunks (pure ALU)
            #pragma unroll
            for (int r = 0; r < 32; r++)
                if (r > c && (keep & cur[r])) pre |= (1u << r);
        }
        if (lane == 0) s_ndet = n < MAX_DET ? n : MAX_DET;
    }
    __syncthreads();
    int n = s_ndet;
    for (int d = tid; d < MAX_DET; d += blockDim.x) {
        if (d < n) {
            int ci = s_det[d];
            int oi = g_oidx[ci];
            float fs = g_topscore[ci];
            float b0 = g_box[ci*4+0], b1 = g_box[ci*4+1], b2 = g_box[ci*4+2], b3 = g_box[ci*4+3];
            int cls = g_cls[ci];
            g_fvalid[d] = 1;
            g_fb[d*4+0]=b0; g_fb[d*4+1]=b1; g_fb[d*4+2]=b2; g_fb[d*4+3]=b3;
            out[OF_FB + d*4+0]=b0; out[OF_FB + d*4+1]=b1; out[OF_FB + d*4+2]=b2; out[OF_FB + d*4+3]=b3;
            out[OF_FS + d] = fs;
            out[OF_FCLS + d] = (float)cls;
            const float* r = pred + (long long)oi*ROW_LEN + 5 + NC;
            for (int k = 0; k < NM; k++) g_fcoef[d*NM+k] = r[k];
        } else {
            g_fvalid[d] = 0;
            g_fb[d*4+0]=0.f; g_fb[d*4+1]=0.f; g_fb[d*4+2]=0.f; g_fb[d*4+3]=0.f;
            out[OF_FB + d*4+0]=0.f; out[OF_FB + d*4+1]=0.f; out[OF_FB + d*4+2]=0.f; out[OF_FB + d*4+3]=0.f;
            out[OF_FS + d] = 0.f;
            out[OF_FCLS + d] = -1.0f;
            for (int k = 0; k < NM; k++) g_fcoef[d*NM+k] = 0.f;
        }
    }
}

// ---------------- K5: mask GEMM + sigmoid, interior-only ----------------
// g_m is only ever read by k_resize for proto rows/cols within the det's box
// (plus a bilinear halo <= 1). Compute only [box/4 - 2, box/4 + 2]; leave the
// rest untouched (never read; crop-masked by select, not arithmetic).
#define GD 16   // dets per block
__global__ void k_gemm(const float* __restrict__ protos) {
    __shared__ float sp[NM][256];
    __shared__ float fc[GD][NM];
    __shared__ int   rg[GD][4];     // ry0, ry1, rx0, rx1 (inclusive)
    int tid = threadIdx.x;
    int p0 = blockIdx.x * 256;
    int d0 = blockIdx.y * GD;
    for (int idx = tid; idx < GD*NM; idx += 256) {
        int dd = idx / NM, k = idx % NM;
        int d = d0 + dd;
        fc[dd][k] = (d < MAX_DET) ? g_fcoef[d*NM + k] : 0.f;
    }
    if (tid < GD) {
        int d = d0 + tid;
        int ry0 = 1, ry1 = 0, rx0 = 1, rx1 = 0;   // empty
        if (d < MAX_DET && g_fvalid[d]) {
            float x1 = g_fb[d*4+0], y1 = g_fb[d*4+1], x2 = g_fb[d*4+2], y2 = g_fb[d*4+3];
            ry0 = max(0, (int)floorf(y1*0.25f) - 2);
            ry1 = min(PROTO_HW-1, (int)floorf(y2*0.25f) + 2);
            rx0 = max(0, (int)floorf(x1*0.25f) - 2);
            rx1 = min(PROTO_HW-1, (int)floorf(x2*0.25f) + 2);
        }
        rg[tid][0] = ry0; rg[tid][1] = ry1; rg[tid][2] = rx0; rg[tid][3] = rx1;
    }
    #pragma unroll 8
    for (int k = 0; k < NM; k++) sp[k][tid] = protos[(long long)k*PROTO_PX + p0 + tid];
    __syncthreads();
    int p = p0 + tid;
    int pr = p / PROTO_HW, pc = p % PROTO_HW;
    #pragma unroll 4
    for (int dd = 0; dd < GD; dd++) {
        int d = d0 + dd;
        if (d >= MAX_DET) break;
        if (pr < rg[dd][0] || pr > rg[dd][1] || pc < rg[dd][2] || pc > rg[dd][3]) continue;
        float acc = 0.f;
        #pragma unroll
        for (int k = 0; k < NM; k++) acc = fmaf(fc[dd][k], sp[k][tid], acc);
        g_m[(long long)d*PROTO_PX + p] = 1.0f / (1.0f + expf(-acc));
    }
}

// ---------------- K6: single-pass resize + crop + write (whole planes, no memset) ----------------
__global__ void k_resize(float* __restrict__ out) {
    int d = blockIdx.y;
    int row = blockIdx.x;
    int t = threadIdx.x;              // 160 threads
    __shared__ float rb[PROTO_HW];

    bool val = g_fvalid[d] != 0;
    float x1 = g_fb[d*4+0], y1 = g_fb[d*4+1], x2 = g_fb[d*4+2], y2 = g_fb[d*4+3];
    float rowf = (float)row;
    bool rowin = val && (rowf >= y1) && (rowf < y2);   // uniform across block

    long long base = (long long)d * (IMG*IMG) + (long long)row * IMG;
    int c0 = t*4;
    if (rowin) {
        float ys = (rowf + 0.5f)*0.25f - 0.5f;
        ys = fminf(fmaxf(ys, 0.f), (float)(PROTO_HW-1));
        int yA = (int)ys;
        float fy = ys - (float)yA;
        int yB = yA + 1; if (yB > PROTO_HW-1) yB = PROTO_HW-1;
        const float* mrow = &g_m[(long long)d*PROTO_PX];
        rb[t] = mrow[yA*PROTO_HW + t]*(1.0f - fy) + mrow[yB*PROTO_HW + t]*fy;
        __syncthreads();
        float4 vf, vb;
        float* pf = (float*)&vf;
        float* pb = (float*)&vb;
        #pragma unroll
        for (int k = 0; k < 4; k++) {
            int col = c0 + k;
            float colf = (float)col;
            float xs = (colf + 0.5f)*0.25f - 0.5f;
            xs = fminf(fmaxf(xs, 0.f), (float)(PROTO_HW-1));
            int xA = (int)xs;
            float fx = xs - (float)xA;
            int xB = xA + 1; if (xB > PROTO_HW-1) xB = PROTO_HW-1;
            float v = rb[xA]*(1.0f - fx) + rb[xB]*fx;
            bool inx = (colf >= x1) && (colf < x2);
            float o = inx ? v : 0.f;
            pf[k] = o;
            pb[k] = (o > 0.5f) ? 1.0f : 0.0f;
        }
        *(float4*)(out + base + c0) = vf;
        *(float4*)(out + OF_BOOL + base + c0) = vb;
    } else {
        float4 z = make_float4(0.f, 0.f, 0.f, 0.f);
        *(float4*)(out + base + c0) = z;
        *(float4*)(out + OF_BOOL + base + c0) = z;
    }
}

// ---------------- launch ----------------
extern "C" void kernel_launch(void* const* d_in, const int* in_sizes, int n_in,
                              void* d_out, int out_size) {
    const float* pred   = (const float*)d_in[0];
    const float* protos = (const float*)d_in[1];
    float* out = (float*)d_out;

    void* histp = nullptr;
    cudaGetSymbolAddress(&histp, g_hist);

    cudaMemsetAsync(histp, 0, 65536 * sizeof(unsigned), 0);
    k_score<<<(N_ANCH*32 + 255)/256, 256>>>(pred);
    k_select<<<1, 1024>>>(pred);
    k_sup<<<TOPK/8, 256>>>();
    k_nms_final<<<1, 256>>>(pred, out);
    k_gemm<<<dim3(PROTO_PX/256, (MAX_DET + GD - 1)/GD), 256>>>(protos);
    k_resize<<<dim3(IMG, MAX_DET), PROTO_HW>>>(out);
}